// round 1
// baseline (speedup 1.0000x reference)
#include <cuda_runtime.h>
#include <math.h>

#define T_    64
#define B_    512
#define NTOK  512
#define NINP  600
#define NHID  600
#define NB    6
#define TOPK_ 4
#define BS_   100
#define ATT   340
#define DK    64
#define DC    32

#define TB    (T_ * B_)          // 32768
#define DEC_OFF   (TB * NTOK)        // 16777216
#define HT_OFF    (DEC_OFF + B_ * NHID)  // 17084416 start of bmask; hT at DEC_OFF

// ---------------- scratch (device globals; no allocation in kernel_launch) ----
__device__ float g_T1[513 * 404];        // [enc_W;enc_b] @ [Wk | Wv]
__device__ float g_W12[513 * 400];       // folded [W1 (100) | W2 (300)], row 512 = bias
__device__ float g_wqkvx[(size_t)TB * 400]; // per-(t,b): wqk (100) | vx (300)
__device__ float g_h[B_ * NHID];         // recurrent state
__device__ float g_out[(size_t)TB * NHID]; // h history for dec GEMM

// ---------------- small helpers ----------------
__global__ void init_h(const float* __restrict__ hidden) {
    int i = blockIdx.x * blockDim.x + threadIdx.x;
    if (i < B_ * NHID) g_h[i] = hidden[i];
}

__global__ void copy_hT(float* __restrict__ dst) {
    int i = blockIdx.x * blockDim.x + threadIdx.x;
    if (i < B_ * NHID) dst[i] = g_h[i];
}

// T1[r][c] : rows 0..511 = enc_W row r, row 512 = enc_b;  cols 0..63 = @Wk, 64..403 = @Wv
__global__ void fold1(const float* __restrict__ enc_W, const float* __restrict__ enc_b,
                      const float* __restrict__ Wk,    const float* __restrict__ Wv) {
    int idx = blockIdx.x * blockDim.x + threadIdx.x;
    if (idx >= 513 * 404) return;
    int r = idx / 404, c = idx % 404;
    const float* arow = (r < 512) ? (enc_W + (size_t)r * NINP) : enc_b;
    float acc = 0.f;
    if (c < 64) {
        #pragma unroll 4
        for (int k = 0; k < NINP; k++) acc += arow[k] * __ldg(&Wk[k * DK + c]);
    } else {
        int cc = c - 64;
        #pragma unroll 4
        for (int k = 0; k < NINP; k++) acc += arow[k] * __ldg(&Wv[k * ATT + cc]);
    }
    g_T1[idx] = acc;
}

// W12[r][c] : c<100 -> T1[:, :64] @ Wq^T ; c>=100 -> T1[:, 64:404] @ Wx
__global__ void fold2(const float* __restrict__ Wq, const float* __restrict__ Wx) {
    int idx = blockIdx.x * blockDim.x + threadIdx.x;
    if (idx >= 513 * 400) return;
    int r = idx / 400, c = idx % 400;
    float acc = 0.f;
    if (c < 100) {
        const float* t1 = g_T1 + r * 404;
        const float* wq = Wq + c * DK;        // Wq is (100,64) row-major; row c contiguous
        #pragma unroll 8
        for (int k = 0; k < DK; k++) acc += t1[k] * wq[k];
    } else {
        const float* t1 = g_T1 + r * 404 + 64;
        int cc = c - 100;
        #pragma unroll 4
        for (int k = 0; k < ATT; k++) acc += t1[k] * __ldg(&Wx[k * 300 + cc]);
    }
    g_W12[idx] = acc;
}

// ---------------- fp32 SGEMM: C[M,N] = A[M,K] @ B[K,N] + bias[N] ----------------
// BM=128 BN=128 BK=8, 256 threads, 8x8 per thread. M % 128 == 0, K % 8 == 0, N % 4 == 0.
__device__ __forceinline__ void sgemm_body(
    const float* __restrict__ A, const float* __restrict__ B,
    const float* __restrict__ bias, float* __restrict__ C,
    int M, int N, int K)
{
    __shared__ float As[8][128];
    __shared__ float Bs[8][128];
    const int tid = threadIdx.x;
    const int m0 = blockIdx.y * 128;
    const int n0 = blockIdx.x * 128;
    const int arow = tid >> 1, acol = (tid & 1) * 4;
    const int brow = tid >> 5, bcol = (tid & 31) * 4;
    const int tm = (tid >> 4) * 8, tn = (tid & 15) * 8;

    float acc[8][8];
    #pragma unroll
    for (int i = 0; i < 8; i++)
        #pragma unroll
        for (int j = 0; j < 8; j++) acc[i][j] = 0.f;

    for (int k0 = 0; k0 < K; k0 += 8) {
        float4 av = *(const float4*)(A + (size_t)(m0 + arow) * K + k0 + acol);
        As[acol + 0][arow] = av.x;
        As[acol + 1][arow] = av.y;
        As[acol + 2][arow] = av.z;
        As[acol + 3][arow] = av.w;
        float4 bv = make_float4(0.f, 0.f, 0.f, 0.f);
        if (n0 + bcol < N)
            bv = *(const float4*)(B + (size_t)(k0 + brow) * N + n0 + bcol);
        *(float4*)&Bs[brow][bcol] = bv;
        __syncthreads();
        #pragma unroll
        for (int k = 0; k < 8; k++) {
            float a[8], b[8];
            *(float4*)(a)     = *(const float4*)&As[k][tm];
            *(float4*)(a + 4) = *(const float4*)&As[k][tm + 4];
            *(float4*)(b)     = *(const float4*)&Bs[k][tn];
            *(float4*)(b + 4) = *(const float4*)&Bs[k][tn + 4];
            #pragma unroll
            for (int i = 0; i < 8; i++)
                #pragma unroll
                for (int j = 0; j < 8; j++)
                    acc[i][j] += a[i] * b[j];
        }
        __syncthreads();
    }
    #pragma unroll
    for (int i = 0; i < 8; i++) {
        int m = m0 + tm + i;
        #pragma unroll
        for (int j = 0; j < 8; j += 4) {
            int n = n0 + tn + j;
            if (n < N) {
                float4 v;
                v.x = acc[i][j + 0] + bias[n + 0];
                v.y = acc[i][j + 1] + bias[n + 1];
                v.z = acc[i][j + 2] + bias[n + 2];
                v.w = acc[i][j + 3] + bias[n + 3];
                *(float4*)(C + (size_t)m * N + n) = v;
            }
        }
    }
}

__global__ __launch_bounds__(256) void gemm_wqkvx(const float* __restrict__ input) {
    sgemm_body(input, g_W12, g_W12 + 512 * 400, g_wqkvx, TB, 400, NTOK);
}

__global__ __launch_bounds__(256) void gemm_dec(const float* __restrict__ dec_W,
                                                const float* __restrict__ dec_b,
                                                float* __restrict__ C) {
    sgemm_body(g_out, dec_W, dec_b, C, TB, NTOK, NHID);
}

// ---------------- recurrent step: 2 batches per block, 320 threads ----------------
__global__ __launch_bounds__(320) void step_kernel(
    int t,
    const float* __restrict__ masks,
    const float* __restrict__ Wh,     // (100,300)
    const float* __restrict__ gru_b,  // (300)
    const float* __restrict__ Wq2,    // (100,32)
    const float* __restrict__ Wk2,    // (100,32)
    const float* __restrict__ Wv2,    // (100,100)
    float* __restrict__ bmask_out)
{
    __shared__ float hb[12][100];
    __shared__ float hn[12][100];
    __shared__ float hg[12][300];
    __shared__ float wqk_s[2][100];
    __shared__ float vx_s[2][300];
    __shared__ float sarr[12], parr[12], bm[12];
    __shared__ float q2[12][32], k2[12][32], v2[12][100];
    __shared__ float p2[12][6];

    const int tid = threadIdx.x;
    const int b0 = blockIdx.x * 2;

    // phase 0: load state (apply mask) + folded inputs
    for (int i = tid; i < 1200; i += 320) {
        int bb = i / 600, j = i % 600;
        float m = masks[t * B_ + b0 + bb];
        hb[bb * 6 + j / 100][j % 100] = g_h[(b0 + bb) * NHID + j] * m;
    }
    for (int i = tid; i < 800; i += 320) {
        int bb = i / 400, c = i % 400;
        float v = g_wqkvx[(size_t)(t * B_ + b0 + bb) * 400 + c];
        if (c < 100) wqk_s[bb][c] = v; else vx_s[bb][c - 100] = v;
    }
    __syncthreads();

    // phase 1: attention-1 score s[b,n] = sc1 * <hb[n], Wq@kk>, p1 = sigmoid(s)
    if (tid < 12) {
        const float* hrow = hb[tid];
        const float* w = wqk_s[tid / 6];
        float s = 0.f;
        #pragma unroll 4
        for (int k = 0; k < 100; k++) s += hrow[k] * w[k];
        s *= 0.125f;                       // 1/sqrt(DK=64)
        sarr[tid] = s;
        parr[tid] = 1.f / (1.f + expf(-s));
    }
    __syncthreads();

    // phase 2: top-k (4 of 6) selection mask; jax top_k tie-break = lower index
    if (tid < 12) {
        int bb = tid / 6, n = tid % 6;
        float sn = sarr[tid];
        int cnt = 0;
        #pragma unroll
        for (int m = 0; m < 6; m++) {
            float sm = sarr[bb * 6 + m];
            if (sm > sn || (sm == sn && m < n)) cnt++;
        }
        float v = (cnt < TOPK_) ? 1.f : 0.f;
        bm[tid] = v;
        bmask_out[(size_t)t * B_ * NB + (b0 + bb) * NB + n] = v;
    }
    __syncthreads();

    // phase 3: hg = hb @ Wh   (12 rows x 300 cols, K=100)
    if (tid < 300) {
        float acc[12];
        #pragma unroll
        for (int u = 0; u < 12; u++) acc[u] = 0.f;
        for (int k = 0; k < 100; k += 4) {
            float w0 = __ldg(&Wh[(k + 0) * 300 + tid]);
            float w1 = __ldg(&Wh[(k + 1) * 300 + tid]);
            float w2 = __ldg(&Wh[(k + 2) * 300 + tid]);
            float w3 = __ldg(&Wh[(k + 3) * 300 + tid]);
            #pragma unroll
            for (int u = 0; u < 12; u++) {
                float4 hv = *(const float4*)&hb[u][k];
                acc[u] += hv.x * w0 + hv.y * w1 + hv.z * w2 + hv.w * w3;
            }
        }
        #pragma unroll
        for (int u = 0; u < 12; u++) hg[u][tid] = acc[u];
    }
    __syncthreads();

    // phase 4: GRU gates (xg = p1*vx + gru_b folded in here)
    for (int i = tid; i < 1200; i += 320) {
        int u = i / 100, j = i % 100;
        int bb = u / 6;
        float p = parr[u];
        float xr = p * vx_s[bb][j]       + gru_b[j];
        float xz = p * vx_s[bb][j + 100] + gru_b[j + 100];
        float xn = p * vx_s[bb][j + 200] + gru_b[j + 200];
        float r  = 1.f / (1.f + expf(-(xr + hg[u][j])));
        float z  = 1.f / (1.f + expf(-(xz + hg[u][j + 100])));
        float nn = tanhf(xn + r * hg[u][j + 200]);
        hn[u][j] = (1.f - z) * nn + z * hb[u][j];
    }
    __syncthreads();

    // phase 5: q2/k2/v2 = hn @ [Wq2 | Wk2 | Wv2]  (164 output cols)
    if (tid < 164) {
        const float* W; int col, ld;
        if (tid < 32)       { W = Wq2; col = tid;      ld = 32; }
        else if (tid < 64)  { W = Wk2; col = tid - 32; ld = 32; }
        else                { W = Wv2; col = tid - 64; ld = 100; }
        float acc[12];
        #pragma unroll
        for (int u = 0; u < 12; u++) acc[u] = 0.f;
        for (int k = 0; k < 100; k += 4) {
            float w0 = __ldg(&W[(k + 0) * ld + col]);
            float w1 = __ldg(&W[(k + 1) * ld + col]);
            float w2 = __ldg(&W[(k + 2) * ld + col]);
            float w3 = __ldg(&W[(k + 3) * ld + col]);
            #pragma unroll
            for (int u = 0; u < 12; u++) {
                float4 hv = *(const float4*)&hn[u][k];
                acc[u] += hv.x * w0 + hv.y * w1 + hv.z * w2 + hv.w * w3;
            }
        }
        #pragma unroll
        for (int u = 0; u < 12; u++) {
            if (tid < 32)      q2[u][col] = acc[u];
            else if (tid < 64) k2[u][col] = acc[u];
            else               v2[u][col] = acc[u];
        }
    }
    __syncthreads();

    // phase 6: attention-2 scores (6x6 per batch)
    if (tid < 72) {
        int bb = tid / 36, nm = tid % 36;
        int n = nm / 6, m = nm % 6;
        const float* qr = q2[bb * 6 + n];
        const float* kr = k2[bb * 6 + m];
        float s = 0.f;
        #pragma unroll
        for (int d = 0; d < 32; d++) s += qr[d] * kr[d];
        p2[bb * 6 + n][m] = s * 0.17677669529663687f;   // 1/sqrt(DC=32)
    }
    __syncthreads();

    // phase 7: softmax over m
    if (tid < 12) {
        float mx = -1e30f;
        #pragma unroll
        for (int m = 0; m < 6; m++) mx = fmaxf(mx, p2[tid][m]);
        float e[6], sum = 0.f;
        #pragma unroll
        for (int m = 0; m < 6; m++) { e[m] = expf(p2[tid][m] - mx); sum += e[m]; }
        float inv = 1.f / sum;
        #pragma unroll
        for (int m = 0; m < 6; m++) p2[tid][m] = e[m] * inv;
    }
    __syncthreads();

    // phase 8: hc = hn + p2@v2; blend by bmask; write h and history
    for (int i = tid; i < 1200; i += 320) {
        int u = i / 100, j = i % 100;
        int bb = u / 6;
        float acc = hn[u][j];
        #pragma unroll
        for (int m = 0; m < 6; m++) acc += p2[u][m] * v2[bb * 6 + m][j];
        float res = (bm[u] > 0.5f) ? acc : hb[u][j];
        int b = b0 + bb;
        int col = (u % 6) * 100 + j;
        g_h[b * NHID + col] = res;
        g_out[((size_t)t * B_ + b) * NHID + col] = res;
    }
}

// ---------------- launch ----------------
extern "C" void kernel_launch(void* const* d_in, const int* in_sizes, int n_in,
                              void* d_out, int out_size) {
    const float* input  = (const float*)d_in[0];
    const float* hidden = (const float*)d_in[1];
    const float* masks  = (const float*)d_in[2];
    const float* enc_W  = (const float*)d_in[3];
    const float* enc_b  = (const float*)d_in[4];
    const float* Wq     = (const float*)d_in[5];
    const float* Wk     = (const float*)d_in[6];
    const float* Wv     = (const float*)d_in[7];
    const float* Wx     = (const float*)d_in[8];
    const float* Wh     = (const float*)d_in[9];
    const float* gru_b  = (const float*)d_in[10];
    const float* Wq2    = (const float*)d_in[11];
    const float* Wk2    = (const float*)d_in[12];
    const float* Wv2    = (const float*)d_in[13];
    const float* dec_W  = (const float*)d_in[14];
    const float* dec_b  = (const float*)d_in[15];
    float* out = (float*)d_out;

    init_h<<<(B_ * NHID + 255) / 256, 256>>>(hidden);
    fold1<<<(513 * 404 + 255) / 256, 256>>>(enc_W, enc_b, Wk, Wv);
    fold2<<<(513 * 400 + 255) / 256, 256>>>(Wq, Wx);

    gemm_wqkvx<<<dim3((400 + 127) / 128, TB / 128), 256>>>(input);

    float* bmask_out = out + DEC_OFF + B_ * NHID;
    for (int t = 0; t < T_; t++) {
        step_kernel<<<B_ / 2, 320>>>(t, masks, Wh, gru_b, Wq2, Wk2, Wv2, bmask_out);
    }

    gemm_dec<<<dim3((NTOK + 127) / 128, TB / 128), 256>>>(dec_W, dec_b, out);
    copy_hT<<<(B_ * NHID + 255) / 256, 256>>>(out + DEC_OFF);
}

// round 2
// speedup vs baseline: 1.0788x; 1.0788x over previous
#include <cuda_runtime.h>
#include <math.h>

#define T_    64
#define B_    512
#define NTOK  512
#define NINP  600
#define NHID  600
#define NB    6
#define TOPK_ 4
#define BS_   100
#define ATT   340
#define DK    64
#define DC    32

#define TB    (T_ * B_)              // 32768
#define DEC_OFF   (TB * NTOK)        // 16777216

// ---------------- scratch (device globals; no allocation in kernel_launch) ----
__device__ float g_T1[513 * 404];           // [enc_W;enc_b] @ [Wk | Wv]
__device__ float g_W12[513 * 400];          // folded [wqk (100) | vx (300)], row 512 = bias
__device__ float g_wqkvx[(size_t)TB * 400]; // per-(t,b): wqk (100) | vx (300)
__device__ float g_out[(size_t)TB * NHID];  // h history for dec GEMM

// ---------------- fold kernels ----------------
// T1[r][c] : rows 0..511 = enc_W row r, row 512 = enc_b;  cols 0..63 = @Wk, 64..403 = @Wv
__global__ void fold1(const float* __restrict__ enc_W, const float* __restrict__ enc_b,
                      const float* __restrict__ Wk,    const float* __restrict__ Wv) {
    int idx = blockIdx.x * blockDim.x + threadIdx.x;
    if (idx >= 513 * 404) return;
    int r = idx / 404, c = idx % 404;
    const float* arow = (r < 512) ? (enc_W + (size_t)r * NINP) : enc_b;
    float acc = 0.f;
    if (c < 64) {
        #pragma unroll 4
        for (int k = 0; k < NINP; k++) acc += arow[k] * __ldg(&Wk[k * DK + c]);
    } else {
        int cc = c - 64;
        #pragma unroll 4
        for (int k = 0; k < NINP; k++) acc += arow[k] * __ldg(&Wv[k * ATT + cc]);
    }
    g_T1[idx] = acc;
}

// W12[r][c] : c<100 -> T1[:, :64] @ Wq^T ; c>=100 -> T1[:, 64:404] @ Wx
__global__ void fold2(const float* __restrict__ Wq, const float* __restrict__ Wx) {
    int idx = blockIdx.x * blockDim.x + threadIdx.x;
    if (idx >= 513 * 400) return;
    int r = idx / 400, c = idx % 400;
    float acc = 0.f;
    if (c < 100) {
        const float* t1 = g_T1 + r * 404;
        const float* wq = Wq + c * DK;   // Wq is (100,64) row-major
        #pragma unroll 8
        for (int k = 0; k < DK; k++) acc += t1[k] * wq[k];
    } else {
        const float* t1 = g_T1 + r * 404 + 64;
        int cc = c - 100;
        #pragma unroll 4
        for (int k = 0; k < ATT; k++) acc += t1[k] * __ldg(&Wx[k * 300 + cc]);
    }
    g_W12[idx] = acc;
}

// ---------------- fp32 SGEMM: C[M,N] = A[M,K] @ B[K,N] + bias[N] ----------------
__device__ __forceinline__ void sgemm_body(
    const float* __restrict__ A, const float* __restrict__ B,
    const float* __restrict__ bias, float* __restrict__ C,
    int M, int N, int K)
{
    __shared__ float As[8][128];
    __shared__ float Bs[8][128];
    const int tid = threadIdx.x;
    const int m0 = blockIdx.y * 128;
    const int n0 = blockIdx.x * 128;
    const int arow = tid >> 1, acol = (tid & 1) * 4;
    const int brow = tid >> 5, bcol = (tid & 31) * 4;
    const int tm = (tid >> 4) * 8, tn = (tid & 15) * 8;

    float acc[8][8];
    #pragma unroll
    for (int i = 0; i < 8; i++)
        #pragma unroll
        for (int j = 0; j < 8; j++) acc[i][j] = 0.f;

    for (int k0 = 0; k0 < K; k0 += 8) {
        float4 av = *(const float4*)(A + (size_t)(m0 + arow) * K + k0 + acol);
        As[acol + 0][arow] = av.x;
        As[acol + 1][arow] = av.y;
        As[acol + 2][arow] = av.z;
        As[acol + 3][arow] = av.w;
        float4 bv = make_float4(0.f, 0.f, 0.f, 0.f);
        if (n0 + bcol < N)
            bv = *(const float4*)(B + (size_t)(k0 + brow) * N + n0 + bcol);
        *(float4*)&Bs[brow][bcol] = bv;
        __syncthreads();
        #pragma unroll
        for (int k = 0; k < 8; k++) {
            float a[8], b[8];
            *(float4*)(a)     = *(const float4*)&As[k][tm];
            *(float4*)(a + 4) = *(const float4*)&As[k][tm + 4];
            *(float4*)(b)     = *(const float4*)&Bs[k][tn];
            *(float4*)(b + 4) = *(const float4*)&Bs[k][tn + 4];
            #pragma unroll
            for (int i = 0; i < 8; i++)
                #pragma unroll
                for (int j = 0; j < 8; j++)
                    acc[i][j] += a[i] * b[j];
        }
        __syncthreads();
    }
    #pragma unroll
    for (int i = 0; i < 8; i++) {
        int m = m0 + tm + i;
        #pragma unroll
        for (int j = 0; j < 8; j += 4) {
            int n = n0 + tn + j;
            if (n < N) {
                float4 v;
                v.x = acc[i][j + 0] + bias[n + 0];
                v.y = acc[i][j + 1] + bias[n + 1];
                v.z = acc[i][j + 2] + bias[n + 2];
                v.w = acc[i][j + 3] + bias[n + 3];
                *(float4*)(C + (size_t)m * N + n) = v;
            }
        }
    }
}

__global__ __launch_bounds__(256) void gemm_wqkvx(const float* __restrict__ input) {
    sgemm_body(input, g_W12, g_W12 + 512 * 400, g_wqkvx, TB, 400, NTOK);
}

__global__ __launch_bounds__(256) void gemm_dec(const float* __restrict__ dec_W,
                                                const float* __restrict__ dec_b,
                                                float* __restrict__ C) {
    sgemm_body(g_out, dec_W, dec_b, C, TB, NTOK, NHID);
}

// ---------------- persistent recurrent kernel: 2 batches/block, all 64 steps ----
__global__ __launch_bounds__(320, 2) void steps_persistent(
    const float* __restrict__ hidden,  // (B, NHID) initial state
    const float* __restrict__ masks,   // (T, B)
    const float* __restrict__ Wh,      // (100,300)
    const float* __restrict__ gru_b,   // (300)
    const float* __restrict__ Wq2,     // (100,32)
    const float* __restrict__ Wk2,     // (100,32)
    const float* __restrict__ Wv2,     // (100,100)
    float* __restrict__ hT_out,        // (B, NHID)
    float* __restrict__ bmask_out)     // (T, B, NB)
{
    __shared__ float hb[12][100];
    __shared__ float hn[12][100];
    __shared__ float hg[12][300];
    __shared__ float wqk_s[2][100];
    __shared__ float vx_s[2][300];
    __shared__ float sarr[12], parr[12], bm[12];
    __shared__ float q2[12][32], k2[12][32], v2[12][100];
    __shared__ float p2[12][6];

    const int tid = threadIdx.x;
    const int b0 = blockIdx.x * 2;

    // initial state load
    for (int i = tid; i < 1200; i += 320) {
        int bb = i / 600, j = i % 600;
        hb[bb * 6 + j / 100][j % 100] = hidden[(b0 + bb) * NHID + j];
    }

    for (int t = 0; t < T_; t++) {
        __syncthreads();   // prev phase-8 writes to hb complete

        // phase 0: mask state in place + load folded inputs for this step
        for (int i = tid; i < 1200; i += 320) {
            int bb = i / 600, j = i % 600;
            float m = masks[t * B_ + b0 + bb];
            hb[bb * 6 + j / 100][j % 100] *= m;
        }
        for (int i = tid; i < 800; i += 320) {
            int bb = i / 400, c = i % 400;
            float v = g_wqkvx[(size_t)(t * B_ + b0 + bb) * 400 + c];
            if (c < 100) wqk_s[bb][c] = v; else vx_s[bb][c - 100] = v;
        }
        __syncthreads();

        // phase 1: s[b,n] = sc1 * <hb[n], wqk>, p1 = sigmoid(s). 16 threads/row.
        if (tid < 192) {
            int u = tid >> 4, l = tid & 15;
            const float* hrow = hb[u];
            const float* w = wqk_s[u / 6];
            float s = 0.f;
            for (int k = l; k < 100; k += 16) s += hrow[k] * w[k];
            s += __shfl_down_sync(0xffffffff, s, 8, 16);
            s += __shfl_down_sync(0xffffffff, s, 4, 16);
            s += __shfl_down_sync(0xffffffff, s, 2, 16);
            s += __shfl_down_sync(0xffffffff, s, 1, 16);
            if (l == 0) {
                s *= 0.125f;               // 1/sqrt(DK=64)
                sarr[u] = s;
                parr[u] = 1.f / (1.f + expf(-s));
            }
        }
        __syncthreads();

        // phase 2 (threads 0..11): top-4-of-6 mask (jax tie-break: lower index wins)
        if (tid < 12) {
            int bb = tid / 6, n = tid % 6;
            float sn = sarr[tid];
            int cnt = 0;
            #pragma unroll
            for (int m = 0; m < 6; m++) {
                float sm = sarr[bb * 6 + m];
                if (sm > sn || (sm == sn && m < n)) cnt++;
            }
            float v = (cnt < TOPK_) ? 1.f : 0.f;
            bm[tid] = v;
            bmask_out[(size_t)t * B_ * NB + (b0 + bb) * NB + n] = v;
        }
        // phase 3 (concurrent, threads 0..299): hg = hb @ Wh
        if (tid < 300) {
            float acc[12];
            #pragma unroll
            for (int u = 0; u < 12; u++) acc[u] = 0.f;
            for (int k = 0; k < 100; k += 4) {
                float w0 = __ldg(&Wh[(k + 0) * 300 + tid]);
                float w1 = __ldg(&Wh[(k + 1) * 300 + tid]);
                float w2 = __ldg(&Wh[(k + 2) * 300 + tid]);
                float w3 = __ldg(&Wh[(k + 3) * 300 + tid]);
                #pragma unroll
                for (int u = 0; u < 12; u++) {
                    float4 hv = *(const float4*)&hb[u][k];
                    acc[u] += hv.x * w0 + hv.y * w1 + hv.z * w2 + hv.w * w3;
                }
            }
            #pragma unroll
            for (int u = 0; u < 12; u++) hg[u][tid] = acc[u];
        }
        __syncthreads();

        // phase 4: GRU gates  (xg = p1*vx + gru_b)
        for (int i = tid; i < 1200; i += 320) {
            int u = i / 100, j = i % 100;
            int bb = u / 6;
            float p = parr[u];
            float xr = p * vx_s[bb][j]       + gru_b[j];
            float xz = p * vx_s[bb][j + 100] + gru_b[j + 100];
            float xn = p * vx_s[bb][j + 200] + gru_b[j + 200];
            float r  = 1.f / (1.f + expf(-(xr + hg[u][j])));
            float z  = 1.f / (1.f + expf(-(xz + hg[u][j + 100])));
            float nn = tanhf(xn + r * hg[u][j + 200]);
            hn[u][j] = (1.f - z) * nn + z * hb[u][j];
        }
        __syncthreads();

        // phase 5: q2/k2/v2 = hn @ [Wq2 | Wk2 | Wv2]
        if (tid < 164) {
            const float* W; int col, ld;
            if (tid < 32)       { W = Wq2; col = tid;      ld = 32; }
            else if (tid < 64)  { W = Wk2; col = tid - 32; ld = 32; }
            else                { W = Wv2; col = tid - 64; ld = 100; }
            float acc[12];
            #pragma unroll
            for (int u = 0; u < 12; u++) acc[u] = 0.f;
            for (int k = 0; k < 100; k += 4) {
                float w0 = __ldg(&W[(k + 0) * ld + col]);
                float w1 = __ldg(&W[(k + 1) * ld + col]);
                float w2 = __ldg(&W[(k + 2) * ld + col]);
                float w3 = __ldg(&W[(k + 3) * ld + col]);
                #pragma unroll
                for (int u = 0; u < 12; u++) {
                    float4 hv = *(const float4*)&hn[u][k];
                    acc[u] += hv.x * w0 + hv.y * w1 + hv.z * w2 + hv.w * w3;
                }
            }
            #pragma unroll
            for (int u = 0; u < 12; u++) {
                if (tid < 32)      q2[u][col] = acc[u];
                else if (tid < 64) k2[u][col] = acc[u];
                else               v2[u][col] = acc[u];
            }
        }
        __syncthreads();

        // phase 6: attention-2 scores (6x6 per batch)
        if (tid < 72) {
            int bb = tid / 36, nm = tid % 36;
            int n = nm / 6, m = nm % 6;
            const float* qr = q2[bb * 6 + n];
            const float* kr = k2[bb * 6 + m];
            float s = 0.f;
            #pragma unroll
            for (int d = 0; d < 32; d++) s += qr[d] * kr[d];
            p2[bb * 6 + n][m] = s * 0.17677669529663687f;   // 1/sqrt(DC=32)
        }
        __syncthreads();

        // phase 7: softmax over m
        if (tid < 12) {
            float mx = -1e30f;
            #pragma unroll
            for (int m = 0; m < 6; m++) mx = fmaxf(mx, p2[tid][m]);
            float e[6], sum = 0.f;
            #pragma unroll
            for (int m = 0; m < 6; m++) { e[m] = expf(p2[tid][m] - mx); sum += e[m]; }
            float inv = 1.f / sum;
            #pragma unroll
            for (int m = 0; m < 6; m++) p2[tid][m] = e[m] * inv;
        }
        __syncthreads();

        // phase 8: hc = hn + p2@v2; blend by bmask; write history + in-place state
        for (int i = tid; i < 1200; i += 320) {
            int u = i / 100, j = i % 100;
            int bb = u / 6;
            float acc = hn[u][j];
            #pragma unroll
            for (int m = 0; m < 6; m++) acc += p2[u][m] * v2[bb * 6 + m][j];
            float res = (bm[u] > 0.5f) ? acc : hb[u][j];
            hb[u][j] = res;
            int b = b0 + bb;
            int col = (u % 6) * 100 + j;
            g_out[((size_t)t * B_ + b) * NHID + col] = res;
        }
    }

    __syncthreads();
    // final hidden state -> output
    for (int i = tid; i < 1200; i += 320) {
        int bb = i / 600, j = i % 600;
        hT_out[(b0 + bb) * NHID + j] = hb[bb * 6 + j / 100][j % 100];
    }
}

// ---------------- launch ----------------
extern "C" void kernel_launch(void* const* d_in, const int* in_sizes, int n_in,
                              void* d_out, int out_size) {
    const float* input  = (const float*)d_in[0];
    const float* hidden = (const float*)d_in[1];
    const float* masks  = (const float*)d_in[2];
    const float* enc_W  = (const float*)d_in[3];
    const float* enc_b  = (const float*)d_in[4];
    const float* Wq     = (const float*)d_in[5];
    const float* Wk     = (const float*)d_in[6];
    const float* Wv     = (const float*)d_in[7];
    const float* Wx     = (const float*)d_in[8];
    const float* Wh     = (const float*)d_in[9];
    const float* gru_b  = (const float*)d_in[10];
    const float* Wq2    = (const float*)d_in[11];
    const float* Wk2    = (const float*)d_in[12];
    const float* Wv2    = (const float*)d_in[13];
    const float* dec_W  = (const float*)d_in[14];
    const float* dec_b  = (const float*)d_in[15];
    float* out = (float*)d_out;

    fold1<<<(513 * 404 + 255) / 256, 256>>>(enc_W, enc_b, Wk, Wv);
    fold2<<<(513 * 400 + 255) / 256, 256>>>(Wq, Wx);

    gemm_wqkvx<<<dim3((400 + 127) / 128, TB / 128), 256>>>(input);

    float* hT_out    = out + DEC_OFF;
    float* bmask_out = out + DEC_OFF + B_ * NHID;
    steps_persistent<<<B_ / 2, 320>>>(hidden, masks, Wh, gru_b, Wq2, Wk2, Wv2,
                                      hT_out, bmask_out);

    gemm_dec<<<dim3((NTOK + 127) / 128, TB / 128), 256>>>(dec_W, dec_b, out);
}